// round 1
// baseline (speedup 1.0000x reference)
#include <cuda_runtime.h>

// FullAttention: causal MHA, B=4, L=2048, H=16, DK=64, fp32.
// Flash-attention-2 style fp32 SIMT baseline (round 0).
// Layouts: q/k/v [B, L, H, DK]; out [B, L, H, DK].

constexpr int Bc = 4, Lc = 2048, Hc = 16, Dc = 64;
constexpr int BM = 64;        // query rows per CTA
constexpr int BN = 64;        // key rows per iteration
constexpr int SST = 68;       // smem row stride (floats): 64 + 4 pad, 16B-aligned
constexpr int NT = 256;       // threads per CTA (16 x 16)
constexpr float LOG2E = 1.44269504f;

__global__ __launch_bounds__(NT, 1)
void fa_fp32_kernel(const float* __restrict__ Qg,
                    const float* __restrict__ Kg,
                    const float* __restrict__ Vg,
                    float* __restrict__ Og) {
    __shared__ float sQ[BM * SST];
    __shared__ float sK[BN * SST];
    __shared__ float sV[BN * SST];
    __shared__ float sP[BM * SST];

    const int tid = threadIdx.x;
    const int tx = tid & 15;          // 0..15: score-col group / output-d group
    const int ty = tid >> 4;          // 0..15: score-row group
    const int tq = blockIdx.x;        // query tile index
    const int h  = blockIdx.y;
    const int b  = blockIdx.z;
    const int q0 = tq * BM;

    const size_t rowstride = (size_t)Hc * Dc;   // stride between seq positions
    const size_t base = ((size_t)b * Lc * Hc + h) * (size_t)Dc;
    const float* Qb = Qg + base;
    const float* Kb = Kg + base;
    const float* Vb = Vg + base;
    float*       Ob = Og + base;

    // ---- Load Q tile (scaled by 1/sqrt(64) = 0.125) ----
    for (int i = tid; i < BM * 16; i += NT) {
        const int r = i >> 4;
        const int c = (i & 15) << 2;
        float4 v = *(const float4*)(Qb + (size_t)(q0 + r) * rowstride + c);
        v.x *= 0.125f; v.y *= 0.125f; v.z *= 0.125f; v.w *= 0.125f;
        *(float4*)(&sQ[r * SST + c]) = v;
    }

    // Per-thread online-softmax state: rows r_i = ty + 16*i, dims d_c = tx*4 + c
    float m_i[4], l_i[4], o[4][4];
    #pragma unroll
    for (int i = 0; i < 4; ++i) {
        m_i[i] = -1e30f;
        l_i[i] = 0.0f;
        #pragma unroll
        for (int c = 0; c < 4; ++c) o[i][c] = 0.0f;
    }

    for (int t = 0; t <= tq; ++t) {
        const int k0 = t * BN;

        __syncthreads();   // prev GEMM2 done with sK/sV/sP; Q ready on iter 0
        // ---- Load K and V tiles ----
        for (int i = tid; i < BN * 16; i += NT) {
            const int r = i >> 4;
            const int c = (i & 15) << 2;
            *(float4*)(&sK[r * SST + c]) =
                *(const float4*)(Kb + (size_t)(k0 + r) * rowstride + c);
            *(float4*)(&sV[r * SST + c]) =
                *(const float4*)(Vb + (size_t)(k0 + r) * rowstride + c);
        }
        __syncthreads();

        // ---- GEMM1: S = Qs @ K^T  (thread frag: rows ty+16i, cols tx+16k) ----
        float s[4][4];
        #pragma unroll
        for (int i = 0; i < 4; ++i)
            #pragma unroll
            for (int k = 0; k < 4; ++k) s[i][k] = 0.0f;

        #pragma unroll 4
        for (int d = 0; d < Dc; d += 4) {
            float4 qf[4], kf[4];
            #pragma unroll
            for (int i = 0; i < 4; ++i)
                qf[i] = *(const float4*)(&sQ[(ty + 16 * i) * SST + d]);
            #pragma unroll
            for (int k = 0; k < 4; ++k)
                kf[k] = *(const float4*)(&sK[(tx + 16 * k) * SST + d]);
            #pragma unroll
            for (int i = 0; i < 4; ++i)
                #pragma unroll
                for (int k = 0; k < 4; ++k)
                    s[i][k] += qf[i].x * kf[k].x + qf[i].y * kf[k].y
                             + qf[i].z * kf[k].z + qf[i].w * kf[k].w;
        }

        // ---- Causal mask on the diagonal tile ----
        if (t == tq) {
            #pragma unroll
            for (int i = 0; i < 4; ++i)
                #pragma unroll
                for (int k = 0; k < 4; ++k)
                    if (tx + 16 * k > ty + 16 * i) s[i][k] = -1e30f;
        }

        // ---- Online softmax update + write P to smem ----
        #pragma unroll
        for (int i = 0; i < 4; ++i) {
            float mx = fmaxf(fmaxf(s[i][0], s[i][1]), fmaxf(s[i][2], s[i][3]));
            mx = fmaxf(mx, __shfl_xor_sync(0xffffffffu, mx, 1));
            mx = fmaxf(mx, __shfl_xor_sync(0xffffffffu, mx, 2));
            mx = fmaxf(mx, __shfl_xor_sync(0xffffffffu, mx, 4));
            mx = fmaxf(mx, __shfl_xor_sync(0xffffffffu, mx, 8));
            const float mn = fmaxf(m_i[i], mx);
            const float alpha = exp2f((m_i[i] - mn) * LOG2E);
            float rs = 0.0f;
            #pragma unroll
            for (int k = 0; k < 4; ++k) {
                const float p = exp2f((s[i][k] - mn) * LOG2E);
                s[i][k] = p;
                rs += p;
            }
            rs += __shfl_xor_sync(0xffffffffu, rs, 1);
            rs += __shfl_xor_sync(0xffffffffu, rs, 2);
            rs += __shfl_xor_sync(0xffffffffu, rs, 4);
            rs += __shfl_xor_sync(0xffffffffu, rs, 8);
            l_i[i] = l_i[i] * alpha + rs;
            m_i[i] = mn;
            #pragma unroll
            for (int c = 0; c < 4; ++c) o[i][c] *= alpha;
            #pragma unroll
            for (int k = 0; k < 4; ++k)
                sP[(ty + 16 * i) * SST + tx + 16 * k] = s[i][k];
        }
        __syncthreads();

        // ---- GEMM2: O += P @ V  (thread frag: rows ty+16i, dims tx*4..tx*4+3) ----
        #pragma unroll 2
        for (int j = 0; j < BN; j += 4) {
            float4 pf4[4], vf4[4];
            #pragma unroll
            for (int i = 0; i < 4; ++i)
                pf4[i] = *(const float4*)(&sP[(ty + 16 * i) * SST + j]);
            #pragma unroll
            for (int jj = 0; jj < 4; ++jj)
                vf4[jj] = *(const float4*)(&sV[(j + jj) * SST + (tx << 2)]);
            #pragma unroll
            for (int i = 0; i < 4; ++i) {
                const float p0 = pf4[i].x, p1 = pf4[i].y, p2 = pf4[i].z, p3 = pf4[i].w;
                o[i][0] += p0 * vf4[0].x + p1 * vf4[1].x + p2 * vf4[2].x + p3 * vf4[3].x;
                o[i][1] += p0 * vf4[0].y + p1 * vf4[1].y + p2 * vf4[2].y + p3 * vf4[3].y;
                o[i][2] += p0 * vf4[0].z + p1 * vf4[1].z + p2 * vf4[2].z + p3 * vf4[3].z;
                o[i][3] += p0 * vf4[0].w + p1 * vf4[1].w + p2 * vf4[2].w + p3 * vf4[3].w;
            }
        }
    }

    // ---- Epilogue: normalize and store ----
    #pragma unroll
    for (int i = 0; i < 4; ++i) {
        const float inv = 1.0f / l_i[i];
        float4 r;
        r.x = o[i][0] * inv;
        r.y = o[i][1] * inv;
        r.z = o[i][2] * inv;
        r.w = o[i][3] * inv;
        *(float4*)(Ob + (size_t)(q0 + ty + 16 * i) * rowstride + (tx << 2)) = r;
    }
}

extern "C" void kernel_launch(void* const* d_in, const int* in_sizes, int n_in,
                              void* d_out, int out_size) {
    const float* q = (const float*)d_in[0];
    const float* k = (const float*)d_in[1];
    const float* v = (const float*)d_in[2];
    float* out = (float*)d_out;
    dim3 grid(Lc / BM, Hc, Bc);   // (32, 16, 4)
    fa_fp32_kernel<<<grid, NT>>>(q, k, v, out);
}

// round 2
// speedup vs baseline: 2.9622x; 2.9622x over previous
#include <cuda_runtime.h>

// FullAttention: causal MHA, B=4, L=2048, H=16, DK=64, fp32 I/O.
// Round 1: tf32 mma.sync (m16n8k8) flash-attention.
// Layouts: q/k/v/out [B, L, H, DK].

constexpr int Bc = 4, Lc = 2048, Hc = 16, Dc = 64;
constexpr int BM = 64;      // query rows per CTA
constexpr int BN = 64;      // key rows per iteration
constexpr int NT = 128;     // 4 warps
constexpr int SK = 68;      // sKP row stride (words)
constexpr int SV = 72;      // sV row stride (words): conflict-free V b-frag loads
constexpr float LOG2E = 1.44269504f;

__device__ __forceinline__ unsigned f2tf(float x) {
    unsigned r;
    asm("cvt.rna.tf32.f32 %0, %1;" : "=r"(r) : "f"(x));
    return r;
}

__device__ __forceinline__ void mma_tf32(float c[4], const unsigned a[4], const unsigned b[2]) {
    asm volatile(
        "mma.sync.aligned.m16n8k8.row.col.f32.tf32.tf32.f32 "
        "{%0,%1,%2,%3}, {%4,%5,%6,%7}, {%8,%9}, {%0,%1,%2,%3};"
        : "+f"(c[0]), "+f"(c[1]), "+f"(c[2]), "+f"(c[3])
        : "r"(a[0]), "r"(a[1]), "r"(a[2]), "r"(a[3]), "r"(b[0]), "r"(b[1]));
}

__global__ __launch_bounds__(NT)
void fa_tf32_kernel(const float* __restrict__ Qg,
                    const float* __restrict__ Kg,
                    const float* __restrict__ Vg,
                    float* __restrict__ Og) {
    // sKP: K tile during GEMM1, P tile during GEMM2 (aliased). tf32 bit patterns.
    __shared__ unsigned sKP[BN * SK];
    __shared__ unsigned sV[BN * SV];

    const int tid  = threadIdx.x;
    const int lane = tid & 31;
    const int w    = tid >> 5;       // warp 0..3
    const int gid  = lane >> 2;      // 0..7
    const int tig  = lane & 3;       // 0..3
    const int m0   = 16 * w;         // warp's row block within tile
    const int tq   = blockIdx.x;
    const int h    = blockIdx.y;
    const int b    = blockIdx.z;
    const int q0   = tq * BM;

    const int rowstride = Hc * Dc;   // 1024
    const size_t base = ((size_t)b * Lc * Hc + h) * (size_t)Dc;
    const float* Qb = Qg + base;
    const float* Kb = Kg + base;
    const float* Vb = Vg + base;
    float*       Ob = Og + base;

    // ---- Stage Q into sKP (scale 1/8 and log2e folded in), then to registers ----
    const float qscale = 0.125f * LOG2E;
    for (int i = tid; i < BM * 16; i += NT) {
        const int r = i >> 4;
        const int c = (i & 15) << 2;
        float4 v = *(const float4*)(Qb + (size_t)(q0 + r) * rowstride + c);
        sKP[r * SK + c + 0] = f2tf(v.x * qscale);
        sKP[r * SK + c + 1] = f2tf(v.y * qscale);
        sKP[r * SK + c + 2] = f2tf(v.z * qscale);
        sKP[r * SK + c + 3] = f2tf(v.w * qscale);
    }
    __syncthreads();

    // Q a-fragments for all 8 k-steps, kept in registers for the whole kernel
    unsigned qa[8][4];
    #pragma unroll
    for (int k = 0; k < 8; ++k) {
        const int kc = 8 * k + tig;
        qa[k][0] = sKP[(m0 + gid)     * SK + kc];
        qa[k][1] = sKP[(m0 + gid + 8) * SK + kc];
        qa[k][2] = sKP[(m0 + gid)     * SK + kc + 4];
        qa[k][3] = sKP[(m0 + gid + 8) * SK + kc + 4];
    }

    float m_[2] = {-1e30f, -1e30f};
    float l_[2] = {0.0f, 0.0f};
    float o[8][4];
    #pragma unroll
    for (int n = 0; n < 8; ++n)
        #pragma unroll
        for (int j = 0; j < 4; ++j) o[n][j] = 0.0f;

    for (int t = 0; t <= tq; ++t) {
        const int k0r = t * BN;

        __syncthreads();   // prev GEMM2 done with sKP/sV (also covers Q frag loads)
        // ---- Load K, V tiles (tf32-rounded) ----
        for (int i = tid; i < BN * 16; i += NT) {
            const int r = i >> 4;
            const int c = (i & 15) << 2;
            float4 kv = *(const float4*)(Kb + (size_t)(k0r + r) * rowstride + c);
            sKP[r * SK + c + 0] = f2tf(kv.x);
            sKP[r * SK + c + 1] = f2tf(kv.y);
            sKP[r * SK + c + 2] = f2tf(kv.z);
            sKP[r * SK + c + 3] = f2tf(kv.w);
            float4 vv = *(const float4*)(Vb + (size_t)(k0r + r) * rowstride + c);
            sV[r * SV + c + 0] = f2tf(vv.x);
            sV[r * SV + c + 1] = f2tf(vv.y);
            sV[r * SV + c + 2] = f2tf(vv.z);
            sV[r * SV + c + 3] = f2tf(vv.w);
        }
        __syncthreads();

        // ---- GEMM1: S(16x64 per warp) = Q @ K^T ----
        float s[8][4];
        #pragma unroll
        for (int n = 0; n < 8; ++n)
            #pragma unroll
            for (int j = 0; j < 4; ++j) s[n][j] = 0.0f;

        #pragma unroll
        for (int k = 0; k < 8; ++k) {
            const int kc = 8 * k + tig;
            #pragma unroll
            for (int n = 0; n < 8; ++n) {
                unsigned bf[2];
                bf[0] = sKP[(8 * n + gid) * SK + kc];
                bf[1] = sKP[(8 * n + gid) * SK + kc + 4];
                mma_tf32(s[n], qa[k], bf);
            }
        }

        // ---- Causal mask (diagonal tile only) ----
        if (t == tq) {
            const int r0 = m0 + gid, r1 = r0 + 8;
            #pragma unroll
            for (int n = 0; n < 8; ++n) {
                const int c0 = 8 * n + 2 * tig;
                if (c0     > r0) s[n][0] = -1e30f;
                if (c0 + 1 > r0) s[n][1] = -1e30f;
                if (c0     > r1) s[n][2] = -1e30f;
                if (c0 + 1 > r1) s[n][3] = -1e30f;
            }
        }

        // ---- Online softmax (log2 domain; scores already *log2e/8) ----
        float mx0 = -1e30f, mx1 = -1e30f;
        #pragma unroll
        for (int n = 0; n < 8; ++n) {
            mx0 = fmaxf(mx0, fmaxf(s[n][0], s[n][1]));
            mx1 = fmaxf(mx1, fmaxf(s[n][2], s[n][3]));
        }
        mx0 = fmaxf(mx0, __shfl_xor_sync(0xffffffffu, mx0, 1));
        mx0 = fmaxf(mx0, __shfl_xor_sync(0xffffffffu, mx0, 2));
        mx1 = fmaxf(mx1, __shfl_xor_sync(0xffffffffu, mx1, 1));
        mx1 = fmaxf(mx1, __shfl_xor_sync(0xffffffffu, mx1, 2));

        const float mn0 = fmaxf(m_[0], mx0);
        const float mn1 = fmaxf(m_[1], mx1);
        const float al0 = exp2f(m_[0] - mn0);
        const float al1 = exp2f(m_[1] - mn1);
        m_[0] = mn0; m_[1] = mn1;

        float rs0 = 0.0f, rs1 = 0.0f;
        #pragma unroll
        for (int n = 0; n < 8; ++n) {
            s[n][0] = exp2f(s[n][0] - mn0); rs0 += s[n][0];
            s[n][1] = exp2f(s[n][1] - mn0); rs0 += s[n][1];
            s[n][2] = exp2f(s[n][2] - mn1); rs1 += s[n][2];
            s[n][3] = exp2f(s[n][3] - mn1); rs1 += s[n][3];
        }
        rs0 += __shfl_xor_sync(0xffffffffu, rs0, 1);
        rs0 += __shfl_xor_sync(0xffffffffu, rs0, 2);
        rs1 += __shfl_xor_sync(0xffffffffu, rs1, 1);
        rs1 += __shfl_xor_sync(0xffffffffu, rs1, 2);
        l_[0] = l_[0] * al0 + rs0;
        l_[1] = l_[1] * al1 + rs1;

        #pragma unroll
        for (int n = 0; n < 8; ++n) {
            o[n][0] *= al0; o[n][1] *= al0;
            o[n][2] *= al1; o[n][3] *= al1;
        }

        __syncthreads();   // all warps done reading K before P overwrites sKP

        // ---- Store P (tf32) into sKP ----
        {
            const int r0 = m0 + gid, r1 = r0 + 8;
            #pragma unroll
            for (int n = 0; n < 8; ++n) {
                const int c0 = 8 * n + 2 * tig;
                uint2 p01 = make_uint2(f2tf(s[n][0]), f2tf(s[n][1]));
                uint2 p23 = make_uint2(f2tf(s[n][2]), f2tf(s[n][3]));
                *(uint2*)&sKP[r0 * SK + c0] = p01;
                *(uint2*)&sKP[r1 * SK + c0] = p23;
            }
        }
        __syncthreads();

        // ---- GEMM2: O(16x64 per warp) += P @ V ----
        #pragma unroll
        for (int k = 0; k < 8; ++k) {
            const int kc = 8 * k + tig;
            unsigned pa[4];
            pa[0] = sKP[(m0 + gid)     * SK + kc];
            pa[1] = sKP[(m0 + gid + 8) * SK + kc];
            pa[2] = sKP[(m0 + gid)     * SK + kc + 4];
            pa[3] = sKP[(m0 + gid + 8) * SK + kc + 4];
            #pragma unroll
            for (int n = 0; n < 8; ++n) {
                unsigned bv[2];
                bv[0] = sV[(8 * k + tig)     * SV + 8 * n + gid];
                bv[1] = sV[(8 * k + tig + 4) * SV + 8 * n + gid];
                mma_tf32(o[n], pa, bv);
            }
        }
    }

    // ---- Epilogue: normalize and store ----
    const float inv0 = 1.0f / l_[0];
    const float inv1 = 1.0f / l_[1];
    const int r0 = q0 + m0 + gid;
    const int r1 = r0 + 8;
    #pragma unroll
    for (int n = 0; n < 8; ++n) {
        const int c0 = 8 * n + 2 * tig;
        float2 v0 = make_float2(o[n][0] * inv0, o[n][1] * inv0);
        float2 v1 = make_float2(o[n][2] * inv1, o[n][3] * inv1);
        *(float2*)(Ob + (size_t)r0 * rowstride + c0) = v0;
        *(float2*)(Ob + (size_t)r1 * rowstride + c0) = v1;
    }
}

extern "C" void kernel_launch(void* const* d_in, const int* in_sizes, int n_in,
                              void* d_out, int out_size) {
    const float* q = (const float*)d_in[0];
    const float* k = (const float*)d_in[1];
    const float* v = (const float*)d_in[2];
    float* out = (float*)d_out;
    dim3 grid(Lc / BM, Hc, Bc);   // (32, 16, 4)
    fa_tf32_kernel<<<grid, NT>>>(q, k, v, out);
}

// round 3
// speedup vs baseline: 5.8756x; 1.9835x over previous
#include <cuda_runtime.h>
#include <cuda_fp16.h>

// FullAttention: causal MHA, B=4, L=2048, H=16, DK=64, fp32 I/O.
// Round 2: fp16 mma.sync (m16n8k16) + ldmatrix + register-resident P.
// Layouts: q/k/v/out [B, L, H, DK].

constexpr int Bc = 4, Lc = 2048, Hc = 16, Dc = 64;
constexpr int BM = 64;      // query rows per CTA
constexpr int BN = 64;      // key rows per iteration
constexpr int NT = 128;     // 4 warps
constexpr int SKH = 72;     // smem row stride in halfs (144 B -> LDSM conflict-free)
constexpr float LOG2E = 1.44269504f;

__device__ __forceinline__ unsigned sptr(const void* p) {
    return (unsigned)__cvta_generic_to_shared(p);
}

__device__ __forceinline__ void ldsm4(unsigned r[4], unsigned addr) {
    asm volatile("ldmatrix.sync.aligned.m8n8.x4.shared.b16 {%0,%1,%2,%3}, [%4];"
                 : "=r"(r[0]), "=r"(r[1]), "=r"(r[2]), "=r"(r[3]) : "r"(addr));
}

__device__ __forceinline__ void ldsm4t(unsigned r[4], unsigned addr) {
    asm volatile("ldmatrix.sync.aligned.m8n8.x4.trans.shared.b16 {%0,%1,%2,%3}, [%4];"
                 : "=r"(r[0]), "=r"(r[1]), "=r"(r[2]), "=r"(r[3]) : "r"(addr));
}

__device__ __forceinline__ void mma_f16(float c[4], const unsigned a[4], const unsigned b[2]) {
    asm volatile(
        "mma.sync.aligned.m16n8k16.row.col.f32.f16.f16.f32 "
        "{%0,%1,%2,%3}, {%4,%5,%6,%7}, {%8,%9}, {%0,%1,%2,%3};"
        : "+f"(c[0]), "+f"(c[1]), "+f"(c[2]), "+f"(c[3])
        : "r"(a[0]), "r"(a[1]), "r"(a[2]), "r"(a[3]), "r"(b[0]), "r"(b[1]));
}

__device__ __forceinline__ unsigned h2u(float lo, float hi) {
    __half2 h = __floats2half2_rn(lo, hi);
    return *(unsigned*)&h;
}

__global__ __launch_bounds__(NT)
void fa_f16_kernel(const float* __restrict__ Qg,
                   const float* __restrict__ Kg,
                   const float* __restrict__ Vg,
                   float* __restrict__ Og) {
    __shared__ __half sK[BN * SKH];   // also Q staging before the main loop
    __shared__ __half sV[BN * SKH];

    const int tid  = threadIdx.x;
    const int lane = tid & 31;
    const int w    = tid >> 5;        // warp 0..3
    const int gid  = lane >> 2;       // 0..7
    const int tig  = lane & 3;        // 0..3
    const int m0   = 16 * w;          // warp's 16-row block
    const int tq   = blockIdx.x;
    const int h    = blockIdx.y;
    const int b    = blockIdx.z;
    const int q0   = tq * BM;

    const int rowstride = Hc * Dc;    // 1024
    const size_t base = ((size_t)b * Lc * Hc + h) * (size_t)Dc;
    const float* Qb = Qg + base;
    const float* Kb = Kg + base;
    const float* Vb = Vg + base;
    float*       Ob = Og + base;

    // ---- Stage Q (scale 1/8 and log2e folded) into sK, then frag to regs ----
    const float qscale = 0.125f * LOG2E;
    for (int i = tid; i < BM * 16; i += NT) {
        const int r = i >> 4;
        const int c = (i & 15) << 2;
        float4 v = *(const float4*)(Qb + (size_t)(q0 + r) * rowstride + c);
        *(uint2*)&sK[r * SKH + c] =
            make_uint2(h2u(v.x * qscale, v.y * qscale), h2u(v.z * qscale, v.w * qscale));
    }
    __syncthreads();

    unsigned qa[4][4];   // a-frags for 4 k16-steps, resident all kernel
    #pragma unroll
    for (int kt = 0; kt < 4; ++kt) {
        unsigned addr = sptr(&sK[(m0 + (lane & 15)) * SKH + 16 * kt + ((lane >> 4) << 3)]);
        ldsm4(qa[kt], addr);
    }

    float m_[2] = {-1e30f, -1e30f};
    float l_[2] = {0.0f, 0.0f};
    float o[8][4];
    #pragma unroll
    for (int n = 0; n < 8; ++n)
        #pragma unroll
        for (int j = 0; j < 4; ++j) o[n][j] = 0.0f;

    for (int t = 0; t <= tq; ++t) {
        const int k0r = t * BN;

        __syncthreads();   // all warps done with sK/sV (covers Q frags on iter 0)
        // ---- Load K, V tiles as fp16 ----
        for (int i = tid; i < BN * 16; i += NT) {
            const int r = i >> 4;
            const int c = (i & 15) << 2;
            float4 kv = *(const float4*)(Kb + (size_t)(k0r + r) * rowstride + c);
            *(uint2*)&sK[r * SKH + c] = make_uint2(h2u(kv.x, kv.y), h2u(kv.z, kv.w));
            float4 vv = *(const float4*)(Vb + (size_t)(k0r + r) * rowstride + c);
            *(uint2*)&sV[r * SKH + c] = make_uint2(h2u(vv.x, vv.y), h2u(vv.z, vv.w));
        }
        __syncthreads();

        // ---- GEMM1: S(16x64 per warp) = Q @ K^T ----
        float s[8][4];
        #pragma unroll
        for (int n = 0; n < 8; ++n)
            #pragma unroll
            for (int j = 0; j < 4; ++j) s[n][j] = 0.0f;

        #pragma unroll
        for (int kt = 0; kt < 4; ++kt) {
            const int k0 = 16 * kt;
            #pragma unroll
            for (int np = 0; np < 4; ++np) {
                // b-frags for n-tiles 16np and 16np+8
                unsigned br[4];
                unsigned addr = sptr(&sK[(16 * np + (lane & 7) + ((lane >> 4) << 3)) * SKH
                                         + k0 + (lane & 8)]);
                ldsm4(br, addr);
                mma_f16(s[2 * np],     qa[kt], br);
                mma_f16(s[2 * np + 1], qa[kt], br + 2);
            }
        }

        // ---- Causal mask (diagonal tile only) ----
        if (t == tq) {
            const int r0 = m0 + gid, r1 = r0 + 8;
            #pragma unroll
            for (int n = 0; n < 8; ++n) {
                const int c0 = 8 * n + 2 * tig;
                if (c0     > r0) s[n][0] = -1e30f;
                if (c0 + 1 > r0) s[n][1] = -1e30f;
                if (c0     > r1) s[n][2] = -1e30f;
                if (c0 + 1 > r1) s[n][3] = -1e30f;
            }
        }

        // ---- Online softmax (log2 domain; scores already *log2e/8) ----
        float mx0 = -1e30f, mx1 = -1e30f;
        #pragma unroll
        for (int n = 0; n < 8; ++n) {
            mx0 = fmaxf(mx0, fmaxf(s[n][0], s[n][1]));
            mx1 = fmaxf(mx1, fmaxf(s[n][2], s[n][3]));
        }
        mx0 = fmaxf(mx0, __shfl_xor_sync(0xffffffffu, mx0, 1));
        mx0 = fmaxf(mx0, __shfl_xor_sync(0xffffffffu, mx0, 2));
        mx1 = fmaxf(mx1, __shfl_xor_sync(0xffffffffu, mx1, 1));
        mx1 = fmaxf(mx1, __shfl_xor_sync(0xffffffffu, mx1, 2));

        const float mn0 = fmaxf(m_[0], mx0);
        const float mn1 = fmaxf(m_[1], mx1);
        const float al0 = exp2f(m_[0] - mn0);
        const float al1 = exp2f(m_[1] - mn1);
        m_[0] = mn0; m_[1] = mn1;

        float rs0 = 0.0f, rs1 = 0.0f;
        #pragma unroll
        for (int n = 0; n < 8; ++n) {
            s[n][0] = exp2f(s[n][0] - mn0); rs0 += s[n][0];
            s[n][1] = exp2f(s[n][1] - mn0); rs0 += s[n][1];
            s[n][2] = exp2f(s[n][2] - mn1); rs1 += s[n][2];
            s[n][3] = exp2f(s[n][3] - mn1); rs1 += s[n][3];
        }
        rs0 += __shfl_xor_sync(0xffffffffu, rs0, 1);
        rs0 += __shfl_xor_sync(0xffffffffu, rs0, 2);
        rs1 += __shfl_xor_sync(0xffffffffu, rs1, 1);
        rs1 += __shfl_xor_sync(0xffffffffu, rs1, 2);
        l_[0] = l_[0] * al0 + rs0;
        l_[1] = l_[1] * al1 + rs1;

        #pragma unroll
        for (int n = 0; n < 8; ++n) {
            o[n][0] *= al0; o[n][1] *= al0;
            o[n][2] *= al1; o[n][3] *= al1;
        }

        // ---- GEMM2: O += P @ V. P comes straight from registers:
        // S c-frag (m=gid,n=2tig+{0,1}) == fp16 a-frag (m=gid,k=2tig+{0,1}). ----
        #pragma unroll
        for (int kt = 0; kt < 4; ++kt) {
            const int k0 = 16 * kt;
            unsigned pa[4];
            pa[0] = h2u(s[2 * kt][0],     s[2 * kt][1]);
            pa[1] = h2u(s[2 * kt][2],     s[2 * kt][3]);
            pa[2] = h2u(s[2 * kt + 1][0], s[2 * kt + 1][1]);
            pa[3] = h2u(s[2 * kt + 1][2], s[2 * kt + 1][3]);
            #pragma unroll
            for (int np = 0; np < 4; ++np) {
                unsigned bv[4];
                unsigned addr = sptr(&sV[(k0 + (lane & 15)) * SKH
                                         + 16 * np + ((lane >> 4) << 3)]);
                ldsm4t(bv, addr);
                mma_f16(o[2 * np],     pa, bv);
                mma_f16(o[2 * np + 1], pa, bv + 2);
            }
        }
    }

    // ---- Epilogue: normalize and store ----
    const float inv0 = 1.0f / l_[0];
    const float inv1 = 1.0f / l_[1];
    const int r0 = q0 + m0 + gid;
    const int r1 = r0 + 8;
    #pragma unroll
    for (int n = 0; n < 8; ++n) {
        const int c0 = 8 * n + 2 * tig;
        float2 v0 = make_float2(o[n][0] * inv0, o[n][1] * inv0);
        float2 v1 = make_float2(o[n][2] * inv1, o[n][3] * inv1);
        *(float2*)(Ob + (size_t)r0 * rowstride + c0) = v0;
        *(float2*)(Ob + (size_t)r1 * rowstride + c0) = v1;
    }
}

extern "C" void kernel_launch(void* const* d_in, const int* in_sizes, int n_in,
                              void* d_out, int out_size) {
    const float* q = (const float*)d_in[0];
    const float* k = (const float*)d_in[1];
    const float* v = (const float*)d_in[2];
    float* out = (float*)d_out;
    dim3 grid(Lc / BM, Hc, Bc);   // (32, 16, 4)
    fa_f16_kernel<<<grid, NT>>>(q, k, v, out);
}

// round 5
// speedup vs baseline: 6.7772x; 1.1534x over previous
#include <cuda_runtime.h>
#include <cuda_fp16.h>

// FullAttention: causal MHA, B=4, L=2048, H=16, DK=64, fp32 I/O.
// Round 3: pre-converted fp16 K/V + cp.async double-buffered pipeline,
//          BM=128 (8 warps), fp16 m16n8k16 mma + ldmatrix, register-resident P.

constexpr int Bc = 4, Lc = 2048, Hc = 16, Dc = 64;
constexpr int BM = 128;     // query rows per CTA
constexpr int BN = 64;      // key rows per iteration
constexpr int NT = 256;     // 8 warps
constexpr int SKH = 72;     // smem row stride in halfs (144 B)
constexpr float LOG2E = 1.44269504f;

// fp16 copies of K and V, produced once per launch by convert_kv.
__device__ __half gK[(size_t)Bc * Lc * Hc * Dc];
__device__ __half gV[(size_t)Bc * Lc * Hc * Dc];

__device__ __forceinline__ unsigned sptr(const void* p) {
    return (unsigned)__cvta_generic_to_shared(p);
}
__device__ __forceinline__ void ldsm4(unsigned r[4], unsigned addr) {
    asm volatile("ldmatrix.sync.aligned.m8n8.x4.shared.b16 {%0,%1,%2,%3}, [%4];"
                 : "=r"(r[0]), "=r"(r[1]), "=r"(r[2]), "=r"(r[3]) : "r"(addr));
}
__device__ __forceinline__ void ldsm4t(unsigned r[4], unsigned addr) {
    asm volatile("ldmatrix.sync.aligned.m8n8.x4.trans.shared.b16 {%0,%1,%2,%3}, [%4];"
                 : "=r"(r[0]), "=r"(r[1]), "=r"(r[2]), "=r"(r[3]) : "r"(addr));
}
__device__ __forceinline__ void mma_f16(float c[4], const unsigned a[4], const unsigned b[2]) {
    asm volatile(
        "mma.sync.aligned.m16n8k16.row.col.f32.f16.f16.f32 "
        "{%0,%1,%2,%3}, {%4,%5,%6,%7}, {%8,%9}, {%0,%1,%2,%3};"
        : "+f"(c[0]), "+f"(c[1]), "+f"(c[2]), "+f"(c[3])
        : "r"(a[0]), "r"(a[1]), "r"(a[2]), "r"(a[3]), "r"(b[0]), "r"(b[1]));
}
__device__ __forceinline__ unsigned h2u(float lo, float hi) {
    __half2 h = __floats2half2_rn(lo, hi);
    return *(unsigned*)&h;
}
__device__ __forceinline__ float ex2(float x) {
    float y;
    asm("ex2.approx.ftz.f32 %0, %1;" : "=f"(y) : "f"(x));
    return y;
}
__device__ __forceinline__ void cpa16(unsigned dst, const void* src) {
    asm volatile("cp.async.ca.shared.global [%0], [%1], 16;" :: "r"(dst), "l"(src));
}
__device__ __forceinline__ void cpa_commit() {
    asm volatile("cp.async.commit_group;");
}

// ---- Kernel 1: fp32 -> fp16 conversion of K and V ----
__global__ __launch_bounds__(256)
void convert_kv(const float* __restrict__ K, const float* __restrict__ V) {
    const int i = blockIdx.x * 256 + threadIdx.x;   // one float4 per thread
    const int n4 = Bc * Lc * Hc * Dc / 4;
    if (i < n4) {
        float4 k4 = ((const float4*)K)[i];
        ((uint2*)gK)[i] = make_uint2(h2u(k4.x, k4.y), h2u(k4.z, k4.w));
        float4 v4 = ((const float4*)V)[i];
        ((uint2*)gV)[i] = make_uint2(h2u(v4.x, v4.y), h2u(v4.z, v4.w));
    }
}

// ---- Kernel 2: flash attention ----
__global__ __launch_bounds__(NT)
void fa_f16_pipe_kernel(const float* __restrict__ Qg, float* __restrict__ Og) {
    __shared__ union {
        struct {
            __half k[2][BN * SKH];
            __half v[2][BN * SKH];
        } s;
        __half q[BM * SKH];     // Q staging (prologue only; overlaps k/v)
    } sm;

    const int tid  = threadIdx.x;
    const int lane = tid & 31;
    const int w    = tid >> 5;        // warp 0..7
    const int gid  = lane >> 2;
    const int tig  = lane & 3;
    const int m0   = 16 * w;          // warp's 16-row block within the 128-row tile
    const int tq   = blockIdx.x;
    const int h    = blockIdx.y;
    const int b    = blockIdx.z;
    const int q0   = tq * BM;

    const int rowstride = Hc * Dc;    // 1024
    const size_t base = ((size_t)b * Lc * Hc + h) * (size_t)Dc;
    const float*  Qb = Qg + base;
    const __half* Kh = gK + base;
    const __half* Vh = gV + base;
    float*        Ob = Og + base;

    // ---- Stage Q (scale 1/8 and log2e folded), fragment to registers ----
    const float qscale = 0.125f * LOG2E;
    for (int i = tid; i < BM * 16; i += NT) {
        const int r = i >> 4;
        const int c = (i & 15) << 2;
        float4 v = *(const float4*)(Qb + (size_t)(q0 + r) * rowstride + c);
        *(uint2*)&sm.q[r * SKH + c] =
            make_uint2(h2u(v.x * qscale, v.y * qscale), h2u(v.z * qscale, v.w * qscale));
    }
    __syncthreads();

    unsigned qa[4][4];
    #pragma unroll
    for (int kt = 0; kt < 4; ++kt)
        ldsm4(qa[kt], sptr(&sm.q[(m0 + (lane & 15)) * SKH + 16 * kt + ((lane >> 4) << 3)]));
    __syncthreads();   // frags extracted before cp.async overwrites the union

    float m_[2] = {-1e30f, -1e30f};
    float l_[2] = {0.0f, 0.0f};
    float o[8][4];
    #pragma unroll
    for (int n = 0; n < 8; ++n)
        #pragma unroll
        for (int j = 0; j < 4; ++j) o[n][j] = 0.0f;

    const int tmax = 2 * tq + 1;

    // ---- Prologue: async-load tile 0 ----
    #pragma unroll
    for (int i = tid; i < 512; i += NT) {          // 64 rows x 8 chunks of 16B
        const int r = i >> 3, c = (i & 7) << 3;
        cpa16(sptr(&sm.s.k[0][r * SKH + c]), Kh + (size_t)r * rowstride + c);
        cpa16(sptr(&sm.s.v[0][r * SKH + c]), Vh + (size_t)r * rowstride + c);
    }
    cpa_commit();

    for (int t = 0; t <= tmax; ++t) {
        const int buf = t & 1;

        // ---- Issue loads for tile t+1 into the other buffer ----
        if (t < tmax) {
            const int k1 = (t + 1) * BN;
            #pragma unroll
            for (int i = tid; i < 512; i += NT) {
                const int r = i >> 3, c = (i & 7) << 3;
                cpa16(sptr(&sm.s.k[buf ^ 1][r * SKH + c]),
                      Kh + (size_t)(k1 + r) * rowstride + c);
                cpa16(sptr(&sm.s.v[buf ^ 1][r * SKH + c]),
                      Vh + (size_t)(k1 + r) * rowstride + c);
            }
            cpa_commit();
            asm volatile("cp.async.wait_group 1;");
        } else {
            asm volatile("cp.async.wait_group 0;");
        }
        __syncthreads();

        // Warps whose 16 rows are entirely above the diagonal in this tile
        // contribute nothing (fully masked) — skip compute, keep barriers.
        const bool active = !(t == tmax && m0 < 64);
        if (active) {
            // ---- GEMM1: S(16x64) = Q @ K^T ----
            float s[8][4];
            #pragma unroll
            for (int n = 0; n < 8; ++n)
                #pragma unroll
                for (int j = 0; j < 4; ++j) s[n][j] = 0.0f;

            #pragma unroll
            for (int kt = 0; kt < 4; ++kt) {
                const int k0 = 16 * kt;
                #pragma unroll
                for (int np = 0; np < 4; ++np) {
                    unsigned br[4];
                    ldsm4(br, sptr(&sm.s.k[buf][(16 * np + (lane & 7) + ((lane >> 4) << 3)) * SKH
                                               + k0 + (lane & 8)]));
                    mma_f16(s[2 * np],     qa[kt], br);
                    mma_f16(s[2 * np + 1], qa[kt], br + 2);
                }
            }

            // ---- Causal mask (only possible on the last two tiles) ----
            if (t >= tmax - 1) {
                const int r0g = q0 + m0 + gid, r1g = r0g + 8;
                const int cb  = t * BN + 2 * tig;
                #pragma unroll
                for (int n = 0; n < 8; ++n) {
                    const int c0 = cb + 8 * n;
                    if (c0     > r0g) s[n][0] = -1e30f;
                    if (c0 + 1 > r0g) s[n][1] = -1e30f;
                    if (c0     > r1g) s[n][2] = -1e30f;
                    if (c0 + 1 > r1g) s[n][3] = -1e30f;
                }
            }

            // ---- Online softmax (log2 domain) ----
            float mx0 = -1e30f, mx1 = -1e30f;
            #pragma unroll
            for (int n = 0; n < 8; ++n) {
                mx0 = fmaxf(mx0, fmaxf(s[n][0], s[n][1]));
                mx1 = fmaxf(mx1, fmaxf(s[n][2], s[n][3]));
            }
            mx0 = fmaxf(mx0, __shfl_xor_sync(0xffffffffu, mx0, 1));
            mx0 = fmaxf(mx0, __shfl_xor_sync(0xffffffffu, mx0, 2));
            mx1 = fmaxf(mx1, __shfl_xor_sync(0xffffffffu, mx1, 1));
            mx1 = fmaxf(mx1, __shfl_xor_sync(0xffffffffu, mx1, 2));

            const float mn0 = fmaxf(m_[0], mx0);
            const float mn1 = fmaxf(m_[1], mx1);
            const float al0 = ex2(m_[0] - mn0);
            const float al1 = ex2(m_[1] - mn1);
            m_[0] = mn0; m_[1] = mn1;

            float rs0 = 0.0f, rs1 = 0.0f;
            #pragma unroll
            for (int n = 0; n < 8; ++n) {
                s[n][0] = ex2(s[n][0] - mn0); rs0 += s[n][0];
                s[n][1] = ex2(s[n][1] - mn0); rs0 += s[n][1];
                s[n][2] = ex2(s[n][2] - mn1); rs1 += s[n][2];
                s[n][3] = ex2(s[n][3] - mn1); rs1 += s[n][3];
            }
            rs0 += __shfl_xor_sync(0xffffffffu, rs0, 1);
            rs0 += __shfl_xor_sync(0xffffffffu, rs0, 2);
            rs1 += __shfl_xor_sync(0xffffffffu, rs1, 1);
            rs1 += __shfl_xor_sync(0xffffffffu, rs1, 2);
            l_[0] = l_[0] * al0 + rs0;
            l_[1] = l_[1] * al1 + rs1;

            #pragma unroll
            for (int n = 0; n < 8; ++n) {
                o[n][0] *= al0; o[n][1] *= al0;
                o[n][2] *= al1; o[n][3] *= al1;
            }

            // ---- GEMM2: O += P @ V, P packed straight from registers ----
            #pragma unroll
            for (int kt = 0; kt < 4; ++kt) {
                const int k0 = 16 * kt;
                unsigned pa[4];
                pa[0] = h2u(s[2 * kt][0],     s[2 * kt][1]);
                pa[1] = h2u(s[2 * kt][2],     s[2 * kt][3]);
                pa[2] = h2u(s[2 * kt + 1][0], s[2 * kt + 1][1]);
                pa[3] = h2u(s[2 * kt + 1][2], s[2 * kt + 1][3]);
                #pragma unroll
                for (int np = 0; np < 4; ++np) {
                    unsigned bv[4];
                    ldsm4t(bv, sptr(&sm.s.v[buf][(k0 + (lane & 15)) * SKH
                                                 + 16 * np + ((lane >> 4) << 3)]));
                    mma_f16(o[2 * np],     pa, bv);
                    mma_f16(o[2 * np + 1], pa, bv + 2);
                }
            }
        }
        __syncthreads();   // all warps done with buf before it is refilled
    }

    // ---- Epilogue: normalize and store ----
    const float inv0 = 1.0f / l_[0];
    const float inv1 = 1.0f / l_[1];
    const int r0 = q0 + m0 + gid;
    const int r1 = r0 + 8;
    #pragma unroll
    for (int n = 0; n < 8; ++n) {
        const int c0 = 8 * n + 2 * tig;
        *(float2*)(Ob + (size_t)r0 * rowstride + c0) =
            make_float2(o[n][0] * inv0, o[n][1] * inv0);
        *(float2*)(Ob + (size_t)r1 * rowstride + c0) =
            make_float2(o[n][2] * inv1, o[n][3] * inv1);
    }
}

extern "C" void kernel_launch(void* const* d_in, const int* in_sizes, int n_in,
                              void* d_out, int out_size) {
    const float* q = (const float*)d_in[0];
    const float* k = (const float*)d_in[1];
    const float* v = (const float*)d_in[2];
    float* out = (float*)d_out;

    const int n4 = Bc * Lc * Hc * Dc / 4;
    convert_kv<<<(n4 + 255) / 256, 256>>>(k, v);

    dim3 grid(Lc / BM, Hc, Bc);   // (16, 16, 4)
    fa_f16_pipe_kernel<<<grid, NT>>>(q, out);
}

// round 7
// speedup vs baseline: 7.0465x; 1.0397x over previous
#include <cuda_runtime.h>
#include <cuda_fp16.h>

// FullAttention: causal MHA, B=4, L=2048, H=16, DK=64, fp32 I/O.
// Round 5: f16x2 exp, ones-MMA row sums, single barrier per pipeline stage.

constexpr int Bc = 4, Lc = 2048, Hc = 16, Dc = 64;
constexpr int BM = 128;     // query rows per CTA
constexpr int BN = 64;      // key rows per iteration
constexpr int NT = 256;     // 8 warps
constexpr int SKH = 72;     // smem row stride in halfs (144 B)
constexpr float LOG2E = 1.44269504f;

// fp16 copies of K and V, produced once per launch by convert_kv.
__device__ __half gK[(size_t)Bc * Lc * Hc * Dc];
__device__ __half gV[(size_t)Bc * Lc * Hc * Dc];

__device__ __forceinline__ unsigned sptr(const void* p) {
    return (unsigned)__cvta_generic_to_shared(p);
}
__device__ __forceinline__ void ldsm4(unsigned r[4], unsigned addr) {
    asm volatile("ldmatrix.sync.aligned.m8n8.x4.shared.b16 {%0,%1,%2,%3}, [%4];"
                 : "=r"(r[0]), "=r"(r[1]), "=r"(r[2]), "=r"(r[3]) : "r"(addr));
}
__device__ __forceinline__ void ldsm4t(unsigned r[4], unsigned addr) {
    asm volatile("ldmatrix.sync.aligned.m8n8.x4.trans.shared.b16 {%0,%1,%2,%3}, [%4];"
                 : "=r"(r[0]), "=r"(r[1]), "=r"(r[2]), "=r"(r[3]) : "r"(addr));
}
__device__ __forceinline__ void mma_f16(float c[4], const unsigned a[4], const unsigned b[2]) {
    asm volatile(
        "mma.sync.aligned.m16n8k16.row.col.f32.f16.f16.f32 "
        "{%0,%1,%2,%3}, {%4,%5,%6,%7}, {%8,%9}, {%0,%1,%2,%3};"
        : "+f"(c[0]), "+f"(c[1]), "+f"(c[2]), "+f"(c[3])
        : "r"(a[0]), "r"(a[1]), "r"(a[2]), "r"(a[3]), "r"(b[0]), "r"(b[1]));
}
__device__ __forceinline__ unsigned h2u(float lo, float hi) {
    __half2 h = __floats2half2_rn(lo, hi);
    return *(unsigned*)&h;
}
__device__ __forceinline__ unsigned ex2h2(unsigned x) {   // packed fp16 2^x
    unsigned y;
    asm("ex2.approx.f16x2 %0, %1;" : "=r"(y) : "r"(x));
    return y;
}
__device__ __forceinline__ float ex2(float x) {
    float y;
    asm("ex2.approx.ftz.f32 %0, %1;" : "=f"(y) : "f"(x));
    return y;
}
__device__ __forceinline__ void cpa16(unsigned dst, const void* src) {
    asm volatile("cp.async.cg.shared.global [%0], [%1], 16;" :: "r"(dst), "l"(src));
}
__device__ __forceinline__ void cpa_commit() {
    asm volatile("cp.async.commit_group;");
}

// ---- Kernel 1: fp32 -> fp16 conversion of K and V ----
__global__ __launch_bounds__(256)
void convert_kv(const float* __restrict__ K, const float* __restrict__ V) {
    const int i = blockIdx.x * 256 + threadIdx.x;   // one float4 per thread
    const int n4 = Bc * Lc * Hc * Dc / 4;
    if (i < n4) {
        float4 k4 = ((const float4*)K)[i];
        ((uint2*)gK)[i] = make_uint2(h2u(k4.x, k4.y), h2u(k4.z, k4.w));
        float4 v4 = ((const float4*)V)[i];
        ((uint2*)gV)[i] = make_uint2(h2u(v4.x, v4.y), h2u(v4.z, v4.w));
    }
}

// ---- Kernel 2: flash attention ----
__global__ __launch_bounds__(NT)
void fa_f16_pipe_kernel(const float* __restrict__ Qg, float* __restrict__ Og) {
    __shared__ union {
        struct {
            __half k[2][BN * SKH];
            __half v[2][BN * SKH];
        } s;
        __half q[BM * SKH];     // Q staging (prologue only; overlaps k/v)
    } sm;

    const int tid  = threadIdx.x;
    const int lane = tid & 31;
    const int w    = tid >> 5;        // warp 0..7
    const int gid  = lane >> 2;
    const int tig  = lane & 3;
    const int m0   = 16 * w;          // warp's 16-row block within the 128-row tile
    const int tq   = blockIdx.x;
    const int h    = blockIdx.y;
    const int b    = blockIdx.z;
    const int q0   = tq * BM;

    const int rowstride = Hc * Dc;    // 1024
    const size_t base = ((size_t)b * Lc * Hc + h) * (size_t)Dc;
    const float*  Qb = Qg + base;
    const __half* Kh = gK + base;
    const __half* Vh = gV + base;
    float*        Ob = Og + base;

    // ---- Stage Q (scale 1/8 and log2e folded), fragment to registers ----
    const float qscale = 0.125f * LOG2E;
    for (int i = tid; i < BM * 16; i += NT) {
        const int r = i >> 4;
        const int c = (i & 15) << 2;
        float4 v = *(const float4*)(Qb + (size_t)(q0 + r) * rowstride + c);
        *(uint2*)&sm.q[r * SKH + c] =
            make_uint2(h2u(v.x * qscale, v.y * qscale), h2u(v.z * qscale, v.w * qscale));
    }
    __syncthreads();

    unsigned qa[4][4];
    #pragma unroll
    for (int kt = 0; kt < 4; ++kt)
        ldsm4(qa[kt], sptr(&sm.q[(m0 + (lane & 15)) * SKH + 16 * kt + ((lane >> 4) << 3)]));
    __syncthreads();   // frags extracted before cp.async overwrites the union

    float m_[2] = {-1e30f, -1e30f};
    float l_[2] = {0.0f, 0.0f};
    float o[8][4];
    #pragma unroll
    for (int n = 0; n < 8; ++n)
        #pragma unroll
        for (int j = 0; j < 4; ++j) o[n][j] = 0.0f;

    const int tmax = 2 * tq + 1;
    const unsigned ones2[2] = {0x3C003C00u, 0x3C003C00u};   // fp16 1.0 x2, all n

    // ---- Prologue: async-load tile 0 ----
    #pragma unroll
    for (int i = tid; i < 512; i += NT) {          // 64 rows x 8 chunks of 16B
        const int r = i >> 3, c = (i & 7) << 3;
        cpa16(sptr(&sm.s.k[0][r * SKH + c]), Kh + (size_t)r * rowstride + c);
        cpa16(sptr(&sm.s.v[0][r * SKH + c]), Vh + (size_t)r * rowstride + c);
    }
    cpa_commit();

    for (int t = 0; t <= tmax; ++t) {
        const int buf = t & 1;

        // tile t is the only outstanding group; drain it, publish, then
        // issue tile t+1 (overlaps with compute below). ONE barrier per iter:
        // it both publishes tile t and guarantees iter t-1 is done with buf^1.
        asm volatile("cp.async.wait_group 0;");
        __syncthreads();

        if (t < tmax) {
            const int k1 = (t + 1) * BN;
            #pragma unroll
            for (int i = tid; i < 512; i += NT) {
                const int r = i >> 3, c = (i & 7) << 3;
                cpa16(sptr(&sm.s.k[buf ^ 1][r * SKH + c]),
                      Kh + (size_t)(k1 + r) * rowstride + c);
                cpa16(sptr(&sm.s.v[buf ^ 1][r * SKH + c]),
                      Vh + (size_t)(k1 + r) * rowstride + c);
            }
            cpa_commit();
        }

        // Warps whose 16 rows are entirely above the diagonal in this tile
        // contribute nothing (fully masked) — skip compute.
        const bool active = !(t == tmax && m0 < 64);
        if (active) {
            // ---- GEMM1: S(16x64) = Q @ K^T ----
            float s[8][4];
            #pragma unroll
            for (int n = 0; n < 8; ++n)
                #pragma unroll
                for (int j = 0; j < 4; ++j) s[n][j] = 0.0f;

            #pragma unroll
            for (int kt = 0; kt < 4; ++kt) {
                const int k0 = 16 * kt;
                #pragma unroll
                for (int np = 0; np < 4; ++np) {
                    unsigned br[4];
                    ldsm4(br, sptr(&sm.s.k[buf][(16 * np + (lane & 7) + ((lane >> 4) << 3)) * SKH
                                               + k0 + (lane & 8)]));
                    mma_f16(s[2 * np],     qa[kt], br);
                    mma_f16(s[2 * np + 1], qa[kt], br + 2);
                }
            }

            // ---- Causal mask (only possible on the last two tiles) ----
            if (t >= tmax - 1) {
                const int r0g = q0 + m0 + gid, r1g = r0g + 8;
                const int cb  = t * BN + 2 * tig;
                #pragma unroll
                for (int n = 0; n < 8; ++n) {
                    const int c0 = cb + 8 * n;
                    if (c0     > r0g) s[n][0] = -1e30f;
                    if (c0 + 1 > r0g) s[n][1] = -1e30f;
                    if (c0     > r1g) s[n][2] = -1e30f;
                    if (c0 + 1 > r1g) s[n][3] = -1e30f;
                }
            }

            // ---- Online softmax: max via shfl, exp in packed f16 ----
            float mx0 = -1e30f, mx1 = -1e30f;
            #pragma unroll
            for (int n = 0; n < 8; ++n) {
                mx0 = fmaxf(mx0, fmaxf(s[n][0], s[n][1]));
                mx1 = fmaxf(mx1, fmaxf(s[n][2], s[n][3]));
            }
            mx0 = fmaxf(mx0, __shfl_xor_sync(0xffffffffu, mx0, 1));
            mx0 = fmaxf(mx0, __shfl_xor_sync(0xffffffffu, mx0, 2));
            mx1 = fmaxf(mx1, __shfl_xor_sync(0xffffffffu, mx1, 1));
            mx1 = fmaxf(mx1, __shfl_xor_sync(0xffffffffu, mx1, 2));

            const float mn0 = fmaxf(m_[0], mx0);
            const float mn1 = fmaxf(m_[1], mx1);
            const float al0 = ex2(m_[0] - mn0);
            const float al1 = ex2(m_[1] - mn1);
            m_[0] = mn0; m_[1] = mn1;

            // P = 2^(s-mn) directly as packed fp16 == GEMM2 a-frag halves.
            unsigned p[8][2];
            #pragma unroll
            for (int n = 0; n < 8; ++n) {
                p[n][0] = ex2h2(h2u(s[n][0] - mn0, s[n][1] - mn0));
                p[n][1] = ex2h2(h2u(s[n][2] - mn1, s[n][3] - mn1));
            }

            // Rescale O before accumulating this tile.
            #pragma unroll
            for (int n = 0; n < 8; ++n) {
                o[n][0] *= al0; o[n][1] *= al0;
                o[n][2] *= al1; o[n][3] *= al1;
            }

            // ---- GEMM2: O += P @ V; row sums rs = P @ 1 via ones-MMA ----
            float rsacc[4] = {0.0f, 0.0f, 0.0f, 0.0f};
            #pragma unroll
            for (int kt = 0; kt < 4; ++kt) {
                const int k0 = 16 * kt;
                unsigned pa[4];
                pa[0] = p[2 * kt][0];
                pa[1] = p[2 * kt][1];
                pa[2] = p[2 * kt + 1][0];
                pa[3] = p[2 * kt + 1][1];
                mma_f16(rsacc, pa, ones2);
                #pragma unroll
                for (int np = 0; np < 4; ++np) {
                    unsigned bv[4];
                    ldsm4t(bv, sptr(&sm.s.v[buf][(k0 + (lane & 15)) * SKH
                                                 + 16 * np + ((lane >> 4) << 3)]));
                    mma_f16(o[2 * np],     pa, bv);
                    mma_f16(o[2 * np + 1], pa, bv + 2);
                }
            }
            l_[0] = l_[0] * al0 + rsacc[0];
            l_[1] = l_[1] * al1 + rsacc[2];
        }
    }

    // ---- Epilogue: normalize and store ----
    const float inv0 = 1.0f / l_[0];
    const float inv1 = 1.0f / l_[1];
    const int r0 = q0 + m0 + gid;
    const int r1 = r0 + 8;
    #pragma unroll
    for (int n = 0; n < 8; ++n) {
        const int c0 = 8 * n + 2 * tig;
        *(float2*)(Ob + (size_t)r0 * rowstride + c0) =
            make_float2(o[n][0] * inv0, o[n][1] * inv0);
        *(float2*)(Ob + (size_t)r1 * rowstride + c0) =
            make_float2(o[n][2] * inv1, o[n][3] * inv1);
    }
}

extern "C" void kernel_launch(void* const* d_in, const int* in_sizes, int n_in,
                              void* d_out, int out_size) {
    const float* q = (const float*)d_in[0];
    const float* k = (const float*)d_in[1];
    const float* v = (const float*)d_in[2];
    float* out = (float*)d_out;

    const int n4 = Bc * Lc * Hc * Dc / 4;
    convert_kv<<<(n4 + 255) / 256, 256>>>(k, v);

    dim3 grid(Lc / BM, Hc, Bc);   // (16, 16, 4)
    fa_f16_pipe_kernel<<<grid, NT>>>(q, out);
}

// round 9
// speedup vs baseline: 7.1886x; 1.0202x over previous
#include <cuda_runtime.h>
#include <cuda_fp16.h>

// FullAttention: causal MHA, B=4, L=2048, H=16, DK=64, fp32 I/O.
// Round 7: fp16-accum GEMM1, fully packed-fp16 softmax, exp fused into GEMM2.

constexpr int Bc = 4, Lc = 2048, Hc = 16, Dc = 64;
constexpr int BM = 128;     // query rows per CTA
constexpr int BN = 64;      // key rows per iteration
constexpr int NT = 256;     // 8 warps
constexpr int SKH = 72;     // smem row stride in halfs (144 B)
constexpr float LOG2E = 1.44269504f;

// fp16 copies of K and V, produced once per launch by convert_kv.
__device__ __half gK[(size_t)Bc * Lc * Hc * Dc];
__device__ __half gV[(size_t)Bc * Lc * Hc * Dc];

__device__ __forceinline__ unsigned sptr(const void* p) {
    return (unsigned)__cvta_generic_to_shared(p);
}
__device__ __forceinline__ void ldsm4(unsigned r[4], unsigned addr) {
    asm volatile("ldmatrix.sync.aligned.m8n8.x4.shared.b16 {%0,%1,%2,%3}, [%4];"
                 : "=r"(r[0]), "=r"(r[1]), "=r"(r[2]), "=r"(r[3]) : "r"(addr));
}
__device__ __forceinline__ void ldsm4t(unsigned r[4], unsigned addr) {
    asm volatile("ldmatrix.sync.aligned.m8n8.x4.trans.shared.b16 {%0,%1,%2,%3}, [%4];"
                 : "=r"(r[0]), "=r"(r[1]), "=r"(r[2]), "=r"(r[3]) : "r"(addr));
}
// fp32-accum mma (GEMM2 / row sums)
__device__ __forceinline__ void mma_f16(float c[4], const unsigned a[4], const unsigned b[2]) {
    asm volatile(
        "mma.sync.aligned.m16n8k16.row.col.f32.f16.f16.f32 "
        "{%0,%1,%2,%3}, {%4,%5,%6,%7}, {%8,%9}, {%0,%1,%2,%3};"
        : "+f"(c[0]), "+f"(c[1]), "+f"(c[2]), "+f"(c[3])
        : "r"(a[0]), "r"(a[1]), "r"(a[2]), "r"(a[3]), "r"(b[0]), "r"(b[1]));
}
// fp16-accum mma (GEMM1): c/d are packed half2 pairs in a-frag layout
__device__ __forceinline__ void mma_f16h(unsigned c[2], const unsigned a[4], const unsigned b[2]) {
    asm volatile(
        "mma.sync.aligned.m16n8k16.row.col.f16.f16.f16.f16 "
        "{%0,%1}, {%2,%3,%4,%5}, {%6,%7}, {%0,%1};"
        : "+r"(c[0]), "+r"(c[1])
        : "r"(a[0]), "r"(a[1]), "r"(a[2]), "r"(a[3]), "r"(b[0]), "r"(b[1]));
}
__device__ __forceinline__ unsigned h2u(float lo, float hi) {
    __half2 h = __floats2half2_rn(lo, hi);
    return *(unsigned*)&h;
}
__device__ __forceinline__ unsigned ex2h2(unsigned x) {   // packed fp16 2^x
    unsigned y;
    asm("ex2.approx.f16x2 %0, %1;" : "=r"(y) : "r"(x));
    return y;
}
__device__ __forceinline__ float ex2(float x) {
    float y;
    asm("ex2.approx.ftz.f32 %0, %1;" : "=f"(y) : "f"(x));
    return y;
}
__device__ __forceinline__ unsigned hsub2u(unsigned a, unsigned b) {
    __half2 r = __hsub2(*(__half2*)&a, *(__half2*)&b);
    return *(unsigned*)&r;
}
__device__ __forceinline__ void cpa16(unsigned dst, const void* src) {
    asm volatile("cp.async.cg.shared.global [%0], [%1], 16;" :: "r"(dst), "l"(src));
}
__device__ __forceinline__ void cpa_commit() {
    asm volatile("cp.async.commit_group;");
}

// ---- Kernel 1: fp32 -> fp16 conversion of K and V ----
__global__ __launch_bounds__(256)
void convert_kv(const float* __restrict__ K, const float* __restrict__ V) {
    const int i = blockIdx.x * 256 + threadIdx.x;   // one float4 per thread
    const int n4 = Bc * Lc * Hc * Dc / 4;
    if (i < n4) {
        float4 k4 = ((const float4*)K)[i];
        ((uint2*)gK)[i] = make_uint2(h2u(k4.x, k4.y), h2u(k4.z, k4.w));
        float4 v4 = ((const float4*)V)[i];
        ((uint2*)gV)[i] = make_uint2(h2u(v4.x, v4.y), h2u(v4.z, v4.w));
    }
}

// ---- Kernel 2: flash attention ----
__global__ __launch_bounds__(NT)
void fa_f16_pipe_kernel(const float* __restrict__ Qg, float* __restrict__ Og) {
    __shared__ union {
        struct {
            __half k[2][BN * SKH];
            __half v[2][BN * SKH];
        } s;
        __half q[BM * SKH];     // Q staging (prologue only; overlaps k/v)
    } sm;

    const int tid  = threadIdx.x;
    const int lane = tid & 31;
    const int w    = tid >> 5;        // warp 0..7
    const int gid  = lane >> 2;
    const int tig  = lane & 3;
    const int m0   = 16 * w;          // warp's 16-row block within the 128-row tile
    const int tq   = blockIdx.x;
    const int h    = blockIdx.y;
    const int b    = blockIdx.z;
    const int q0   = tq * BM;

    const int rowstride = Hc * Dc;    // 1024
    const size_t base = ((size_t)b * Lc * Hc + h) * (size_t)Dc;
    const float*  Qb = Qg + base;
    const __half* Kh = gK + base;
    const __half* Vh = gV + base;
    float*        Ob = Og + base;

    // ---- Stage Q (scale 1/8 and log2e folded), fragment to registers ----
    const float qscale = 0.125f * LOG2E;
    for (int i = tid; i < BM * 16; i += NT) {
        const int r = i >> 4;
        const int c = (i & 15) << 2;
        float4 v = *(const float4*)(Qb + (size_t)(q0 + r) * rowstride + c);
        *(uint2*)&sm.q[r * SKH + c] =
            make_uint2(h2u(v.x * qscale, v.y * qscale), h2u(v.z * qscale, v.w * qscale));
    }
    __syncthreads();

    unsigned qa[4][4];
    #pragma unroll
    for (int kt = 0; kt < 4; ++kt)
        ldsm4(qa[kt], sptr(&sm.q[(m0 + (lane & 15)) * SKH + 16 * kt + ((lane >> 4) << 3)]));
    __syncthreads();   // frags extracted before cp.async overwrites the union

    __half2 m_pack = __halves2half2(__ushort_as_half(0xFC00), __ushort_as_half(0xFC00));
    float l_[2] = {0.0f, 0.0f};
    float o[8][4];
    #pragma unroll
    for (int n = 0; n < 8; ++n)
        #pragma unroll
        for (int j = 0; j < 4; ++j) o[n][j] = 0.0f;

    const int tmax = 2 * tq + 1;
    const unsigned ones2[2] = {0x3C003C00u, 0x3C003C00u};   // fp16 1.0 x2

    // ---- Prologue: async-load tile 0 ----
    #pragma unroll
    for (int i = tid; i < 512; i += NT) {          // 64 rows x 8 chunks of 16B
        const int r = i >> 3, c = (i & 7) << 3;
        cpa16(sptr(&sm.s.k[0][r * SKH + c]), Kh + (size_t)r * rowstride + c);
        cpa16(sptr(&sm.s.v[0][r * SKH + c]), Vh + (size_t)r * rowstride + c);
    }
    cpa_commit();

    for (int t = 0; t <= tmax; ++t) {
        const int buf = t & 1;

        asm volatile("cp.async.wait_group 0;");
        __syncthreads();   // publishes tile t; iter t-1 done with buf^1

        if (t < tmax) {
            const int k1 = (t + 1) * BN;
            #pragma unroll
            for (int i = tid; i < 512; i += NT) {
                const int r = i >> 3, c = (i & 7) << 3;
                cpa16(sptr(&sm.s.k[buf ^ 1][r * SKH + c]),
                      Kh + (size_t)(k1 + r) * rowstride + c);
                cpa16(sptr(&sm.s.v[buf ^ 1][r * SKH + c]),
                      Vh + (size_t)(k1 + r) * rowstride + c);
            }
            cpa_commit();
        }

        const bool active = !(t == tmax && m0 < 64);
        if (active) {
            // ---- GEMM1 (fp16 accum): S(16x64) = Q @ K^T, packed half2 ----
            unsigned s[8][2];
            #pragma unroll
            for (int n = 0; n < 8; ++n) { s[n][0] = 0u; s[n][1] = 0u; }

            #pragma unroll
            for (int kt = 0; kt < 4; ++kt) {
                const int k0 = 16 * kt;
                #pragma unroll
                for (int np = 0; np < 4; ++np) {
                    unsigned br[4];
                    ldsm4(br, sptr(&sm.s.k[buf][(16 * np + (lane & 7) + ((lane >> 4) << 3)) * SKH
                                               + k0 + (lane & 8)]));
                    mma_f16h(s[2 * np],     qa[kt], br);
                    mma_f16h(s[2 * np + 1], qa[kt], br + 2);
                }
            }

            // ---- Causal mask (packed; only possible on the last two tiles) ----
            if (t >= tmax - 1) {
                const int r0g = q0 + m0 + gid, r1g = r0g + 8;
                const int cb  = t * BN + 2 * tig;
                const __half NI = __ushort_as_half(0xFC00);
                #pragma unroll
                for (int n = 0; n < 8; ++n) {
                    const int c0 = cb + 8 * n;
                    __half2 v0 = *(__half2*)&s[n][0];
                    __half2 v1 = *(__half2*)&s[n][1];
                    if (c0     > r0g) v0.x = NI;
                    if (c0 + 1 > r0g) v0.y = NI;
                    if (c0     > r1g) v1.x = NI;
                    if (c0 + 1 > r1g) v1.y = NI;
                    s[n][0] = *(unsigned*)&v0;
                    s[n][1] = *(unsigned*)&v1;
                }
            }

            // ---- Packed max reduction (rows gid, gid+8 together) ----
            __half2 a0 = *(__half2*)&s[0][0];
            __half2 a1 = *(__half2*)&s[0][1];
            #pragma unroll
            for (int n = 1; n < 8; ++n) {
                a0 = __hmax2(a0, *(__half2*)&s[n][0]);
                a1 = __hmax2(a1, *(__half2*)&s[n][1]);
            }
            __half2 mx = __halves2half2(__hmax(__low2half(a0), __high2half(a0)),
                                        __hmax(__low2half(a1), __high2half(a1)));
            {
                unsigned mu = *(unsigned*)&mx;
                unsigned t1 = __shfl_xor_sync(0xffffffffu, mu, 1);
                mx = __hmax2(mx, *(__half2*)&t1);
                mu = *(unsigned*)&mx;
                unsigned t2 = __shfl_xor_sync(0xffffffffu, mu, 2);
                mx = __hmax2(mx, *(__half2*)&t2);
            }
            const __half2 mn = __hmax2(m_pack, mx);
            const float al0 = ex2(__low2float(m_pack)  - __low2float(mn));
            const float al1 = ex2(__high2float(m_pack) - __high2float(mn));
            m_pack = mn;
            const __half2 mnb0h = __half2half2(__low2half(mn));
            const __half2 mnb1h = __half2half2(__high2half(mn));
            const unsigned mnb0 = *(const unsigned*)&mnb0h;
            const unsigned mnb1 = *(const unsigned*)&mnb1h;

            // Rescale O before accumulating this tile.
            #pragma unroll
            for (int n = 0; n < 8; ++n) {
                o[n][0] *= al0; o[n][1] *= al0;
                o[n][2] *= al1; o[n][3] *= al1;
            }

            // ---- exp fused into GEMM2: O += P @ V; rs = P @ 1 ----
            float rsacc[4] = {0.0f, 0.0f, 0.0f, 0.0f};
            #pragma unroll
            for (int kt = 0; kt < 4; ++kt) {
                const int k0 = 16 * kt;
                unsigned pa[4];
                pa[0] = ex2h2(hsub2u(s[2 * kt][0],     mnb0));
                pa[1] = ex2h2(hsub2u(s[2 * kt][1],     mnb1));
                pa[2] = ex2h2(hsub2u(s[2 * kt + 1][0], mnb0));
                pa[3] = ex2h2(hsub2u(s[2 * kt + 1][1], mnb1));
                mma_f16(rsacc, pa, ones2);
                #pragma unroll
                for (int np = 0; np < 4; ++np) {
                    unsigned bv[4];
                    ldsm4t(bv, sptr(&sm.s.v[buf][(k0 + (lane & 15)) * SKH
                                                 + 16 * np + ((lane >> 4) << 3)]));
                    mma_f16(o[2 * np],     pa, bv);
                    mma_f16(o[2 * np + 1], pa, bv + 2);
                }
            }
            l_[0] = l_[0] * al0 + rsacc[0];
            l_[1] = l_[1] * al1 + rsacc[2];
        }
    }

    // ---- Epilogue: normalize and store ----
    const float inv0 = 1.0f / l_[0];
    const float inv1 = 1.0f / l_[1];
    const int r0 = q0 + m0 + gid;
    const int r1 = r0 + 8;
    #pragma unroll
    for (int n = 0; n < 8; ++n) {
        const int c0 = 8 * n + 2 * tig;
        *(float2*)(Ob + (size_t)r0 * rowstride + c0) =
            make_float2(o[n][0] * inv0, o[n][1] * inv0);
        *(float2*)(Ob + (size_t)r1 * rowstride + c0) =
            make_float2(o[n][2] * inv1, o[n][3] * inv1);
    }
}

extern "C" void kernel_launch(void* const* d_in, const int* in_sizes, int n_in,
                              void* d_out, int out_size) {
    const float* q = (const float*)d_in[0];
    const float* k = (const float*)d_in[1];
    const float* v = (const float*)d_in[2];
    float* out = (float*)d_out;

    const int n4 = Bc * Lc * Hc * Dc / 4;
    convert_kv<<<(n4 + 255) / 256, 256>>>(k, v);

    dim3 grid(Lc / BM, Hc, Bc);   // (16, 16, 4)
    fa_f16_pipe_kernel<<<grid, NT>>>(q, out);
}